// round 8
// baseline (speedup 1.0000x reference)
#include <cuda_runtime.h>

namespace {
constexpr int W      = 512;
constexpr int H      = 512;
constexpr int PLANES = 16 * 3;         // 48
constexpr int NBLK   = 296;            // 148 SMs x occ 2, exactly one wave
constexpr int NT     = 256;
constexpr int RB     = 528;            // row buffer floats (stride mult of 16B)
constexpr int MAXRI  = 96;             // max riter = 86 + 10
constexpr float C1c  = 1e-4f;
constexpr float C2c  = 9e-4f;
}

__device__ float g_partials[NBLK];
__device__ int   g_count = 0;

// ---------------- packed f32x2 helpers (sm_103a) ----------------
using u64 = unsigned long long;

static __device__ __forceinline__ u64 pk2(float lo, float hi) {
    u64 r; asm("mov.b64 %0, {%1, %2};" : "=l"(r) : "f"(lo), "f"(hi)); return r;
}
static __device__ __forceinline__ u64 pkf2(float2 v) { return pk2(v.x, v.y); }
static __device__ __forceinline__ void upk2(u64 v, float& lo, float& hi) {
    asm("mov.b64 {%0, %1}, %2;" : "=f"(lo), "=f"(hi) : "l"(v));
}
static __device__ __forceinline__ u64 fma2(u64 a, u64 b, u64 c) {
    u64 d; asm("fma.rn.f32x2 %0, %1, %2, %3;" : "=l"(d) : "l"(a), "l"(b), "l"(c)); return d;
}
static __device__ __forceinline__ u64 add2(u64 a, u64 b) {
    u64 d; asm("add.rn.f32x2 %0, %1, %2;" : "=l"(d) : "l"(a), "l"(b)); return d;
}
static __device__ __forceinline__ u64 mul2(u64 a, u64 b) {
    u64 d; asm("mul.rn.f32x2 %0, %1, %2;" : "=l"(d) : "l"(a), "l"(b)); return d;
}
// (a.hi, b.lo) as a packed pair
static __device__ __forceinline__ u64 hilo(u64 a, u64 b) {
    float al, ah, bl, bh; upk2(a, al, ah); upk2(b, bl, bh); return pk2(ah, bl);
}

// Vertical 11-tap blur, split so LDS batches can interleave between halves.
static __device__ __forceinline__ void vert_xy(const u64 xr[11], const u64 yr[11],
                                               int kk, const u64 Wv[6],
                                               u64& vx, u64& vy) {
    const int sC = (kk + 6) % 11;
    vx = mul2(Wv[5], xr[sC]);
    vy = mul2(Wv[5], yr[sC]);
#pragma unroll
    for (int j = 0; j < 5; ++j) {
        const int sA = (kk + 1 + j) % 11;    // row offset j
        const int sB = (kk + 11 - j) % 11;   // row offset 10-j
        vx = fma2(Wv[j], add2(xr[sA], xr[sB]), vx);
        vy = fma2(Wv[j], add2(yr[sA], yr[sB]), vy);
    }
}
static __device__ __forceinline__ void vert_pq(const u64 xr[11], const u64 yr[11],
                                               int kk, const u64 Wv[6],
                                               u64& vp, u64& vq) {
    const int sC = (kk + 6) % 11;
    const u64 xc = xr[sC], yc = yr[sC];
    vp = mul2(Wv[5], fma2(xc, xc, mul2(yc, yc)));
    vq = mul2(Wv[5], mul2(xc, yc));
#pragma unroll
    for (int j = 0; j < 5; ++j) {
        const int sA = (kk + 1 + j) % 11;
        const int sB = (kk + 11 - j) % 11;
        const u64 xa = xr[sA], xb = xr[sB];
        const u64 ya = yr[sA], yb = yr[sB];
        vp = fma2(Wv[j], add2(fma2(xa, xa, mul2(ya, ya)),
                              fma2(xb, xb, mul2(yb, yb))), vp);
        vq = fma2(Wv[j], fma2(xa, ya, mul2(xb, yb)), vq);
    }
}

// Horizontal load / compute split (load issued early, consumed later).
struct HF { float4 a, b, c, d; };
static __device__ __forceinline__ HF hload(const float* rowq, int u) {
    const float4* P = reinterpret_cast<const float4*>(rowq) + u;
    HF f; f.a = P[0]; f.b = P[1]; f.c = P[2]; f.d = P[3]; return f;
}
static __device__ __forceinline__ void hcomp(const HF& f, const u64 Wv[6],
                                             u64& hA, u64& hB) {
    // U_j = cols (4u-6+2j, 4u-5+2j), j=0..7
    const u64 U0 = pk2(f.a.x, f.a.y), U1 = pk2(f.a.z, f.a.w);
    const u64 U2 = pk2(f.b.x, f.b.y), U3 = pk2(f.b.z, f.b.w);
    const u64 U4 = pk2(f.c.x, f.c.y), U5 = pk2(f.c.z, f.c.w);
    const u64 U6 = pk2(f.d.x, f.d.y), U7 = pk2(f.d.z, f.d.w);
    const u64 A2 = add2(U2, U3), A3 = add2(U3, U4), A4 = add2(U4, U5);
    const u64 B1 = add2(U1, U4), B2 = add2(U2, U5), B3 = add2(U3, U6);
    const u64 C0 = add2(U0, U5), C1 = add2(U1, U6), C2 = add2(U2, U7);
    // m = 0 (cols 4u, 4u+1)
    u64 h = mul2(Wv[5], U3);
    h = fma2(Wv[3], add2(U2, U4), h);
    h = fma2(Wv[1], add2(U1, U5), h);
    h = fma2(Wv[4], hilo(A2, A3), h);
    h = fma2(Wv[2], hilo(B1, B2), h);
    h = fma2(Wv[0], hilo(C0, C1), h);
    hA = h;
    // m = 1 (cols 4u+2, 4u+3)
    u64 g = mul2(Wv[5], U4);
    g = fma2(Wv[3], add2(U3, U5), g);
    g = fma2(Wv[1], add2(U2, U6), g);
    g = fma2(Wv[4], hilo(A3, A4), g);
    g = fma2(Wv[2], hilo(B2, B3), g);
    g = fma2(Wv[0], hilo(C1, C2), g);
    hB = g;
}

// h[0]=mu_x, h[1]=mu_y, h[2]=blur(x^2+y^2), h[3]=blur(xy)
static __device__ __forceinline__ float ssim2(u64 h0, u64 h1, u64 h2, u64 h3,
                                              u64 C1_2, u64 C2_2, u64 EPS2, u64 NEG1) {
    const u64 musq = fma2(h0, h0, mul2(h1, h1));
    const u64 mxy  = mul2(h0, h1);
    const u64 ssum = fma2(musq, NEG1, h2);
    const u64 sxy  = fma2(mxy,  NEG1, h3);
    const u64 num = mul2(add2(add2(mxy, mxy), C1_2), add2(add2(sxy, sxy), C2_2));
    const u64 den = add2(mul2(add2(musq, C1_2), add2(ssum, C2_2)), EPS2);
    float n0, n1, d0, d1;
    upk2(num, n0, n1);
    upk2(den, d0, d1);
    return __fdividef(n0, d0) + __fdividef(n1, d1);
}

__global__ __launch_bounds__(NT, 2)
void ssim_main(const float* __restrict__ X, const float* __restrict__ Y,
               float* __restrict__ out) {
    // Double-buffered 2-row exchange: [buffer][row-in-phase][quantity][RB]
    __shared__ __align__(16) float sq[2][2][4][RB];
    __shared__ float wsum[NT / 32];
    __shared__ int amLast;

    const int t = threadIdx.x;              // vertical role: cols (2t, 2t+1)
    const int b = blockIdx.x;               // 0..295

    // ---- Balanced tiling: planes 0-7 have 7 chunks, planes 8-47 have 6 ----
    int plane, r0, ch;
    if (b < 56) {
        plane = b / 7;
        const int c = b % 7;                 // sizes 74,74,74,74,72,72,72
        ch = (c < 4) ? 74 : 72;
        r0 = (c < 4) ? 74 * c : 296 + 72 * (c - 4);
    } else {
        const int bb = b - 56;
        plane = 8 + bb / 6;
        const int c = bb % 6;                // sizes 86,86,86,86,84,84
        ch = (c < 4) ? 86 : 84;
        r0 = (c < 4) ? 86 * c : 344 + 84 * (c - 4);
    }
    const int riter = ch + 10;               // even

    const int hrow = t >> 7;                // horizontal role: row-in-phase
    const int u    = t & 127;               // horizontal role: cols 4u..4u+3

    const float2* __restrict__ X2 =
        reinterpret_cast<const float2*>(X + (size_t)plane * W * H);
    const float2* __restrict__ Y2 =
        reinterpret_cast<const float2*>(Y + (size_t)plane * W * H);

    // Zero pads once (stores below only touch idx [6 .. 517]).
    if (t < 6) {
#pragma unroll
        for (int pb = 0; pb < 2; ++pb)
#pragma unroll
            for (int r = 0; r < 2; ++r)
#pragma unroll
                for (int q = 0; q < 4; ++q) sq[pb][r][q][t] = 0.f;
    }
    if (t < 10) {
#pragma unroll
        for (int pb = 0; pb < 2; ++pb)
#pragma unroll
            for (int r = 0; r < 2; ++r)
#pragma unroll
                for (int q = 0; q < 4; ++q) sq[pb][r][q][518 + t] = 0.f;
    }

    const float Gw[6] = {0.00102838f, 0.00759875f, 0.03600077f,
                         0.10936070f, 0.21300554f, 0.26601172f};
    u64 Wv[6];
#pragma unroll
    for (int i = 0; i < 6; ++i) Wv[i] = pk2(Gw[i], Gw[i]);
    const u64 NEG1 = pk2(-1.f, -1.f);
    const u64 C1_2 = pk2(C1c, C1c);
    const u64 C2_2 = pk2(C2c, C2c);
    const u64 EPS2 = pk2(1e-8f, 1e-8f);

    // Register ring: 11 rows of raw x,y (packed column pair).
    u64 xr[11], yr[11];

    // Prefetch rows 0,1 (image rows r0-5, r0-4).
    float2 p0x, p0y, p1x, p1y;
    {
        const int ra = r0 - 5, rb = r0 - 4;
        const bool oa = ((unsigned)ra < (unsigned)H);
        const bool ob = ((unsigned)rb < (unsigned)H);
        p0x = oa ? X2[(size_t)ra * (W / 2) + t] : make_float2(0.f, 0.f);
        p0y = oa ? Y2[(size_t)ra * (W / 2) + t] : make_float2(0.f, 0.f);
        p1x = ob ? X2[(size_t)rb * (W / 2) + t] : make_float2(0.f, 0.f);
        p1y = ob ? Y2[(size_t)rb * (W / 2) + t] : make_float2(0.f, 0.f);
    }

    float acc = 0.f;

    // Pipelined phases: phase rr computes vert(rr, rr+1) -> STS, and
    // horiz+epilogue for out rows rr-12, rr-11 (stored 2 phases earlier).
#pragma unroll 1
    for (int outer = 0; outer < MAXRI; outer += 22) {
#pragma unroll
        for (int ph = 0; ph < 11; ++ph) {
            const int rr = outer + 2 * ph;
            if (rr < riter) {
                const int k0 = (2 * ph) % 11;
                const int k1 = (2 * ph + 1) % 11;
                const int pbW = (rr >> 1) & 1, pbR = pbW ^ 1;
                const bool doV = (rr >= 10);
                const bool doH = (rr >= 12);

                xr[k0] = pkf2(p0x); yr[k0] = pkf2(p0y);

                if (doH) __syncthreads();   // orders STS(rr-2) before reads

                u64 V0x, V0y, V0p, V0q, V1x, V1y, V1p, V1q;
                u64 h0A, h0B, h1A, h1B, h2A, h2B, h3A, h3B;
                HF f;

                // q0 load -> vert(k0).xy (hides LDS) -> q0 compute
                if (doH) f = hload(&sq[pbR][hrow][0][0], u);
                if (doV) vert_xy(xr, yr, k0, Wv, V0x, V0y);
                if (doH) { hcomp(f, Wv, h0A, h0B); f = hload(&sq[pbR][hrow][1][0], u); }
                if (doV) vert_pq(xr, yr, k0, Wv, V0p, V0q);
                if (doH) hcomp(f, Wv, h1A, h1B);

                // vert(k0) done reading slot k1 (row rr-10): safe to overwrite.
                xr[k1] = pkf2(p1x); yr[k1] = pkf2(p1y);

                // Prefetch rows rr+2, rr+3 (consumed next phase).
                {
                    const int ra = r0 - 5 + rr + 2, rb = ra + 1;
                    const bool oa = (rr + 2 < riter) && ((unsigned)ra < (unsigned)H);
                    const bool ob = (rr + 3 < riter) && ((unsigned)rb < (unsigned)H);
                    p0x = oa ? X2[(size_t)ra * (W / 2) + t] : make_float2(0.f, 0.f);
                    p0y = oa ? Y2[(size_t)ra * (W / 2) + t] : make_float2(0.f, 0.f);
                    p1x = ob ? X2[(size_t)rb * (W / 2) + t] : make_float2(0.f, 0.f);
                    p1y = ob ? Y2[(size_t)rb * (W / 2) + t] : make_float2(0.f, 0.f);
                }

                if (doH) f = hload(&sq[pbR][hrow][2][0], u);
                if (doV) vert_xy(xr, yr, k1, Wv, V1x, V1y);
                if (doH) { hcomp(f, Wv, h2A, h2B); f = hload(&sq[pbR][hrow][3][0], u); }
                if (doV) vert_pq(xr, yr, k1, Wv, V1p, V1q);
                if (doH) {
                    hcomp(f, Wv, h3A, h3B);
                    acc += ssim2(h0A, h1A, h2A, h3A, C1_2, C2_2, EPS2, NEG1);
                    acc += ssim2(h0B, h1B, h2B, h3B, C1_2, C2_2, EPS2, NEG1);
                }

                if (doV) {   // store vert results for out rows rr-10, rr-9
                    float* s00 = &sq[pbW][0][0][6 + 2 * t];
                    float* s10 = &sq[pbW][1][0][6 + 2 * t];
                    *reinterpret_cast<u64*>(s00 + 0 * RB) = V0x;
                    *reinterpret_cast<u64*>(s00 + 1 * RB) = V0y;
                    *reinterpret_cast<u64*>(s00 + 2 * RB) = V0p;
                    *reinterpret_cast<u64*>(s00 + 3 * RB) = V0q;
                    *reinterpret_cast<u64*>(s10 + 0 * RB) = V1x;
                    *reinterpret_cast<u64*>(s10 + 1 * RB) = V1y;
                    *reinterpret_cast<u64*>(s10 + 2 * RB) = V1p;
                    *reinterpret_cast<u64*>(s10 + 3 * RB) = V1q;
                }
            }
        }
    }

    // ---- Drain: out rows riter-12, riter-11 (stored at phase riter-2) ----
    __syncthreads();
    {
        const int pbD = ((riter - 2) >> 1) & 1;
        u64 hA[4], hB[4];
#pragma unroll
        for (int q = 0; q < 4; ++q) {
            HF f = hload(&sq[pbD][hrow][q][0], u);
            hcomp(f, Wv, hA[q], hB[q]);
        }
        acc += ssim2(hA[0], hA[1], hA[2], hA[3], C1_2, C2_2, EPS2, NEG1);
        acc += ssim2(hB[0], hB[1], hB[2], hB[3], C1_2, C2_2, EPS2, NEG1);
    }

    // ---- Deterministic block reduction ----
#pragma unroll
    for (int off = 16; off > 0; off >>= 1)
        acc += __shfl_down_sync(0xffffffffu, acc, off);
    const int lane = t & 31, wid = t >> 5;
    if (lane == 0) wsum[wid] = acc;
    __syncthreads();
    if (wid == 0) {
        float v = (lane < NT / 32) ? wsum[lane] : 0.f;
#pragma unroll
        for (int off = 4; off > 0; off >>= 1)
            v += __shfl_down_sync(0xffffffffu, v, off);
        if (lane == 0) g_partials[b] = v;
    }

    // ---- Fused finalize: last block reduces all partials ----
    if (t == 0) {
        __threadfence();
        const int prev = atomicAdd(&g_count, 1);
        amLast = (prev == NBLK - 1);
    }
    __syncthreads();
    if (amLast) {
        float s = (t < NBLK) ? g_partials[t] : 0.f;
        if (t + 256 < NBLK) s += g_partials[t + 256];
#pragma unroll
        for (int off = 16; off > 0; off >>= 1)
            s += __shfl_down_sync(0xffffffffu, s, off);
        if (lane == 0) wsum[wid] = s;
        __syncthreads();
        if (wid == 0) {
            float v = (lane < NT / 32) ? wsum[lane] : 0.f;
#pragma unroll
            for (int off = 4; off > 0; off >>= 1)
                v += __shfl_down_sync(0xffffffffu, v, off);
            if (lane == 0) {
                constexpr float invN = 1.0f / (float)((size_t)PLANES * W * H);
                out[0] = 1.0f - v * invN;
                g_count = 0;        // reset for next graph replay
            }
        }
    }
}

extern "C" void kernel_launch(void* const* d_in, const int* in_sizes, int n_in,
                              void* d_out, int out_size) {
    const float* X = (const float*)d_in[0];
    const float* Y = (const float*)d_in[1];
    float* out = (float*)d_out;

    ssim_main<<<NBLK, NT>>>(X, Y, out);   // 296 blocks = 148 SMs x occ 2
}

// round 9
// speedup vs baseline: 1.0058x; 1.0058x over previous
#include <cuda_runtime.h>

namespace {
constexpr int W      = 512;
constexpr int H      = 512;
constexpr int PLANES = 16 * 3;         // 48
constexpr int NBLK   = 296;            // 148 SMs x occ 2, exactly one wave
constexpr int NT     = 256;
constexpr int RB     = 528;            // row buffer floats (stride mult of 16B)
constexpr int MAXRI  = 96;             // max riter = 86 + 10
constexpr float C1c  = 1e-4f;
constexpr float C2c  = 9e-4f;
}

__device__ float g_partials[NBLK];
__device__ int   g_count = 0;

// ---------------- packed f32x2 helpers (sm_103a) ----------------
using u64 = unsigned long long;

static __device__ __forceinline__ u64 pk2(float lo, float hi) {
    u64 r; asm("mov.b64 %0, {%1, %2};" : "=l"(r) : "f"(lo), "f"(hi)); return r;
}
static __device__ __forceinline__ u64 pkf2(float2 v) { return pk2(v.x, v.y); }
static __device__ __forceinline__ void upk2(u64 v, float& lo, float& hi) {
    asm("mov.b64 {%0, %1}, %2;" : "=f"(lo), "=f"(hi) : "l"(v));
}
static __device__ __forceinline__ u64 fma2(u64 a, u64 b, u64 c) {
    u64 d; asm("fma.rn.f32x2 %0, %1, %2, %3;" : "=l"(d) : "l"(a), "l"(b), "l"(c)); return d;
}
static __device__ __forceinline__ u64 add2(u64 a, u64 b) {
    u64 d; asm("add.rn.f32x2 %0, %1, %2;" : "=l"(d) : "l"(a), "l"(b)); return d;
}
static __device__ __forceinline__ u64 mul2(u64 a, u64 b) {
    u64 d; asm("mul.rn.f32x2 %0, %1, %2;" : "=l"(d) : "l"(a), "l"(b)); return d;
}
// (a.hi, b.lo) as a packed pair
static __device__ __forceinline__ u64 hilo(u64 a, u64 b) {
    float al, ah, bl, bh; upk2(a, al, ah); upk2(b, bl, bh); return pk2(ah, bl);
}

// Vertical 11-tap blur of x, y, p = x^2+y^2, q = x*y from the register ring.
static __device__ __forceinline__ void vert(const u64 xr[11], const u64 yr[11],
                                            int kk, const u64 Wv[6], u64 v[4]) {
    const int sC = (kk + 6) % 11;
    const u64 xc = xr[sC], yc = yr[sC];
    v[0] = mul2(Wv[5], xc);
    v[1] = mul2(Wv[5], yc);
    v[2] = mul2(Wv[5], fma2(xc, xc, mul2(yc, yc)));
    v[3] = mul2(Wv[5], mul2(xc, yc));
#pragma unroll
    for (int j = 0; j < 5; ++j) {
        const int sA = (kk + 1 + j) % 11;    // row offset j
        const int sB = (kk + 11 - j) % 11;   // row offset 10-j
        const u64 xa = xr[sA], xb = xr[sB];
        const u64 ya = yr[sA], yb = yr[sB];
        v[0] = fma2(Wv[j], add2(xa, xb), v[0]);
        v[1] = fma2(Wv[j], add2(ya, yb), v[1]);
        const u64 pa = fma2(xa, xa, mul2(ya, ya));
        const u64 pb = fma2(xb, xb, mul2(yb, yb));
        v[2] = fma2(Wv[j], add2(pa, pb), v[2]);
        v[3] = fma2(Wv[j], fma2(xa, ya, mul2(xb, yb)), v[3]);
    }
}

// Horizontal load / compute split (load issued early, consumed later).
struct HF { float4 a, b, c, d; };
static __device__ __forceinline__ HF hload(const float* rowq, int u) {
    const float4* P = reinterpret_cast<const float4*>(rowq) + u;
    HF f; f.a = P[0]; f.b = P[1]; f.c = P[2]; f.d = P[3]; return f;
}
static __device__ __forceinline__ void hcomp(const HF& f, const u64 Wv[6],
                                             u64& hA, u64& hB) {
    // U_j = cols (4u-6+2j, 4u-5+2j), j=0..7
    const u64 U0 = pk2(f.a.x, f.a.y), U1 = pk2(f.a.z, f.a.w);
    const u64 U2 = pk2(f.b.x, f.b.y), U3 = pk2(f.b.z, f.b.w);
    const u64 U4 = pk2(f.c.x, f.c.y), U5 = pk2(f.c.z, f.c.w);
    const u64 U6 = pk2(f.d.x, f.d.y), U7 = pk2(f.d.z, f.d.w);
    const u64 A2 = add2(U2, U3), A3 = add2(U3, U4), A4 = add2(U4, U5);
    const u64 B1 = add2(U1, U4), B2 = add2(U2, U5), B3 = add2(U3, U6);
    const u64 C0 = add2(U0, U5), C1 = add2(U1, U6), C2 = add2(U2, U7);
    // m = 0 (cols 4u, 4u+1)
    u64 h = mul2(Wv[5], U3);
    h = fma2(Wv[3], add2(U2, U4), h);
    h = fma2(Wv[1], add2(U1, U5), h);
    h = fma2(Wv[4], hilo(A2, A3), h);
    h = fma2(Wv[2], hilo(B1, B2), h);
    h = fma2(Wv[0], hilo(C0, C1), h);
    hA = h;
    // m = 1 (cols 4u+2, 4u+3)
    u64 g = mul2(Wv[5], U4);
    g = fma2(Wv[3], add2(U3, U5), g);
    g = fma2(Wv[1], add2(U2, U6), g);
    g = fma2(Wv[4], hilo(A3, A4), g);
    g = fma2(Wv[2], hilo(B2, B3), g);
    g = fma2(Wv[0], hilo(C1, C2), g);
    hB = g;
}

// h0=mu_x, h1=mu_y, h2=blur(x^2+y^2), h3=blur(xy)
static __device__ __forceinline__ float ssim2(u64 h0, u64 h1, u64 h2, u64 h3,
                                              u64 C1_2, u64 C2_2, u64 EPS2, u64 NEG1) {
    const u64 musq = fma2(h0, h0, mul2(h1, h1));
    const u64 mxy  = mul2(h0, h1);
    const u64 ssum = fma2(musq, NEG1, h2);
    const u64 sxy  = fma2(mxy,  NEG1, h3);
    const u64 num = mul2(add2(add2(mxy, mxy), C1_2), add2(add2(sxy, sxy), C2_2));
    const u64 den = add2(mul2(add2(musq, C1_2), add2(ssum, C2_2)), EPS2);
    float n0, n1, d0, d1;
    upk2(num, n0, n1);
    upk2(den, d0, d1);
    return __fdividef(n0, d0) + __fdividef(n1, d1);
}

__global__ __launch_bounds__(NT, 2)
void ssim_main(const float* __restrict__ X, const float* __restrict__ Y,
               float* __restrict__ out) {
    // Double-buffered 2-row exchange: [buffer][row-in-phase][quantity][RB]
    __shared__ __align__(16) float sq[2][2][4][RB];
    __shared__ float wsum[NT / 32];
    __shared__ int amLast;

    const int t = threadIdx.x;              // vertical role: cols (2t, 2t+1)
    const int b = blockIdx.x;               // 0..295

    // ---- Balanced tiling: planes 0-7 have 7 chunks, planes 8-47 have 6 ----
    int plane, r0, ch;
    if (b < 56) {
        plane = b / 7;
        const int c = b % 7;                 // sizes 74,74,74,74,72,72,72
        ch = (c < 4) ? 74 : 72;
        r0 = (c < 4) ? 74 * c : 296 + 72 * (c - 4);
    } else {
        const int bb = b - 56;
        plane = 8 + bb / 6;
        const int c = bb % 6;                // sizes 86,86,86,86,84,84
        ch = (c < 4) ? 86 : 84;
        r0 = (c < 4) ? 86 * c : 344 + 84 * (c - 4);
    }
    const int riter = ch + 10;

    const int hrow = t >> 7;                // horizontal role: row-in-phase
    const int u    = t & 127;               // horizontal role: cols 4u..4u+3

    const float2* __restrict__ X2 =
        reinterpret_cast<const float2*>(X + (size_t)plane * W * H);
    const float2* __restrict__ Y2 =
        reinterpret_cast<const float2*>(Y + (size_t)plane * W * H);

    // Zero pads once (stores below only touch idx [6 .. 517]).
    if (t < 6) {
#pragma unroll
        for (int pb = 0; pb < 2; ++pb)
#pragma unroll
            for (int r = 0; r < 2; ++r)
#pragma unroll
                for (int q = 0; q < 4; ++q) sq[pb][r][q][t] = 0.f;
    }
    if (t < 10) {
#pragma unroll
        for (int pb = 0; pb < 2; ++pb)
#pragma unroll
            for (int r = 0; r < 2; ++r)
#pragma unroll
                for (int q = 0; q < 4; ++q) sq[pb][r][q][518 + t] = 0.f;
    }

    const float Gw[6] = {0.00102838f, 0.00759875f, 0.03600077f,
                         0.10936070f, 0.21300554f, 0.26601172f};
    u64 Wv[6];
#pragma unroll
    for (int i = 0; i < 6; ++i) Wv[i] = pk2(Gw[i], Gw[i]);
    const u64 NEG1 = pk2(-1.f, -1.f);
    const u64 C1_2 = pk2(C1c, C1c);
    const u64 C2_2 = pk2(C2c, C2c);
    const u64 EPS2 = pk2(1e-8f, 1e-8f);

    // Register ring: 11 rows of raw x,y (packed column pair).
    u64 xr[11], yr[11];

    // Prefetch rows 0,1 (image rows r0-5, r0-4).
    float2 p0x, p0y, p1x, p1y;
    {
        const int ra = r0 - 5, rb = r0 - 4;
        const bool oa = ((unsigned)ra < (unsigned)H);
        const bool ob = ((unsigned)rb < (unsigned)H);
        p0x = oa ? X2[(size_t)ra * (W / 2) + t] : make_float2(0.f, 0.f);
        p0y = oa ? Y2[(size_t)ra * (W / 2) + t] : make_float2(0.f, 0.f);
        p1x = ob ? X2[(size_t)rb * (W / 2) + t] : make_float2(0.f, 0.f);
        p1y = ob ? Y2[(size_t)rb * (W / 2) + t] : make_float2(0.f, 0.f);
    }

    float acc = 0.f;

#pragma unroll 1
    for (int outer = 0; outer < MAXRI; outer += 22) {
#pragma unroll
        for (int ph = 0; ph < 11; ++ph) {
            const int rr = outer + 2 * ph;          // even; rows rr, rr+1
            if (rr < riter) {
                const int k0 = (2 * ph) % 11;       // compile-time slots
                const int k1 = (2 * ph + 1) % 11;

                // Tap-order fix: vert(k0) must read slot k1 = row rr-10
                // BEFORE it is overwritten with row rr+1.
                xr[k0] = pkf2(p0x); yr[k0] = pkf2(p0y);

                u64 v0[4], v1[4];
                if (rr >= 10) vert(xr, yr, k0, Wv, v0);

                xr[k1] = pkf2(p1x); yr[k1] = pkf2(p1y);

                // Prefetch rows rr+2, rr+3 (hidden under vert/barrier).
                {
                    const int ra = r0 - 5 + rr + 2, rb = ra + 1;
                    const bool oa = (rr + 2 < riter) && ((unsigned)ra < (unsigned)H);
                    const bool ob = (rr + 3 < riter) && ((unsigned)rb < (unsigned)H);
                    p0x = oa ? X2[(size_t)ra * (W / 2) + t] : make_float2(0.f, 0.f);
                    p0y = oa ? Y2[(size_t)ra * (W / 2) + t] : make_float2(0.f, 0.f);
                    p1x = ob ? X2[(size_t)rb * (W / 2) + t] : make_float2(0.f, 0.f);
                    p1y = ob ? Y2[(size_t)rb * (W / 2) + t] : make_float2(0.f, 0.f);
                }

                if (rr >= 10) {
                    vert(xr, yr, k1, Wv, v1);

                    const int pb = (rr >> 1) & 1;   // phase buffer

                    // ---- Exchange: aligned STS.64 (idx 6+2t is even) ----
#pragma unroll
                    for (int q = 0; q < 4; ++q) {
                        *reinterpret_cast<u64*>(&sq[pb][0][q][6 + 2 * t]) = v0[q];
                        *reinterpret_cast<u64*>(&sq[pb][1][q][6 + 2 * t]) = v1[q];
                    }
                    __syncthreads();     // one barrier per 2-row phase

                    // ---- Horizontal, software-pipelined loads ----
                    const float* base = &sq[pb][hrow][0][0];
                    u64 h0A, h0B, h1A, h1B, h2A, h2B, h3A, h3B;
                    HF f0 = hload(base + 0 * RB, u);
                    HF f1 = hload(base + 1 * RB, u);
                    hcomp(f0, Wv, h0A, h0B);
                    f0 = hload(base + 2 * RB, u);
                    hcomp(f1, Wv, h1A, h1B);
                    f1 = hload(base + 3 * RB, u);
                    hcomp(f0, Wv, h2A, h2B);
                    hcomp(f1, Wv, h3A, h3B);

                    acc += ssim2(h0A, h1A, h2A, h3A, C1_2, C2_2, EPS2, NEG1);
                    acc += ssim2(h0B, h1B, h2B, h3B, C1_2, C2_2, EPS2, NEG1);
                    // No second barrier: double-buffered across phases.
                }
            }
        }
    }

    // ---- Deterministic block reduction ----
#pragma unroll
    for (int off = 16; off > 0; off >>= 1)
        acc += __shfl_down_sync(0xffffffffu, acc, off);
    const int lane = t & 31, wid = t >> 5;
    if (lane == 0) wsum[wid] = acc;
    __syncthreads();
    if (wid == 0) {
        float v = (lane < NT / 32) ? wsum[lane] : 0.f;
#pragma unroll
        for (int off = 4; off > 0; off >>= 1)
            v += __shfl_down_sync(0xffffffffu, v, off);
        if (lane == 0) g_partials[b] = v;
    }

    // ---- Fused finalize: last block reduces all partials ----
    if (t == 0) {
        __threadfence();
        const int prev = atomicAdd(&g_count, 1);
        amLast = (prev == NBLK - 1);
    }
    __syncthreads();
    if (amLast) {
        float s = (t < NBLK) ? g_partials[t] : 0.f;
        if (t + 256 < NBLK) s += g_partials[t + 256];
#pragma unroll
        for (int off = 16; off > 0; off >>= 1)
            s += __shfl_down_sync(0xffffffffu, s, off);
        if (lane == 0) wsum[wid] = s;
        __syncthreads();
        if (wid == 0) {
            float v = (lane < NT / 32) ? wsum[lane] : 0.f;
#pragma unroll
            for (int off = 4; off > 0; off >>= 1)
                v += __shfl_down_sync(0xffffffffu, v, off);
            if (lane == 0) {
                constexpr float invN = 1.0f / (float)((size_t)PLANES * W * H);
                out[0] = 1.0f - v * invN;
                g_count = 0;        // reset for next graph replay
            }
        }
    }
}

extern "C" void kernel_launch(void* const* d_in, const int* in_sizes, int n_in,
                              void* d_out, int out_size) {
    const float* X = (const float*)d_in[0];
    const float* Y = (const float*)d_in[1];
    float* out = (float*)d_out;

    ssim_main<<<NBLK, NT>>>(X, Y, out);   // 296 blocks = 148 SMs x occ 2
}

// round 10
// speedup vs baseline: 1.0602x; 1.0541x over previous
#include <cuda_runtime.h>

namespace {
constexpr int W      = 512;
constexpr int H      = 512;
constexpr int PLANES = 16 * 3;         // 48
constexpr int NBLK   = 296;            // 148 SMs x occ 2, exactly one wave
constexpr int NT     = 256;
constexpr int RB     = 528;            // row buffer floats (stride mult of 16B)
constexpr int MAXRI  = 96;             // max riter = 86 + 10
constexpr float C1c  = 1e-4f;
constexpr float C2c  = 9e-4f;
}

__device__ float g_partials[NBLK];
__device__ int   g_count = 0;

// ---------------- packed f32x2 helpers (sm_103a) ----------------
using u64 = unsigned long long;

static __device__ __forceinline__ u64 pk2(float lo, float hi) {
    u64 r; asm("mov.b64 %0, {%1, %2};" : "=l"(r) : "f"(lo), "f"(hi)); return r;
}
static __device__ __forceinline__ u64 pkf2(float2 v) { return pk2(v.x, v.y); }
static __device__ __forceinline__ void upk2(u64 v, float& lo, float& hi) {
    asm("mov.b64 {%0, %1}, %2;" : "=f"(lo), "=f"(hi) : "l"(v));
}
static __device__ __forceinline__ u64 fma2(u64 a, u64 b, u64 c) {
    u64 d; asm("fma.rn.f32x2 %0, %1, %2, %3;" : "=l"(d) : "l"(a), "l"(b), "l"(c)); return d;
}
static __device__ __forceinline__ u64 add2(u64 a, u64 b) {
    u64 d; asm("add.rn.f32x2 %0, %1, %2;" : "=l"(d) : "l"(a), "l"(b)); return d;
}
static __device__ __forceinline__ u64 mul2(u64 a, u64 b) {
    u64 d; asm("mul.rn.f32x2 %0, %1, %2;" : "=l"(d) : "l"(a), "l"(b)); return d;
}
// (a.hi, b.lo) as a packed pair
static __device__ __forceinline__ u64 hilo(u64 a, u64 b) {
    float al, ah, bl, bh; upk2(a, al, ah); upk2(b, bl, bh); return pk2(ah, bl);
}

// Vertical 11-tap blur of x, y, p = x^2+y^2, q = x*y from the register ring.
// The j=0 "oldest row" tap (slot (kk+1)%11) reads from (ox, oy) instead:
// that slot may already hold the next phase's row (R5-style write order).
static __device__ __forceinline__ void vert(const u64 xr[11], const u64 yr[11],
                                            u64 ox, u64 oy, bool useOld,
                                            int kk, const u64 Wv[6], u64 v[4]) {
    const int sC = (kk + 6) % 11;
    const u64 xc = xr[sC], yc = yr[sC];
    v[0] = mul2(Wv[5], xc);
    v[1] = mul2(Wv[5], yc);
    v[2] = mul2(Wv[5], fma2(xc, xc, mul2(yc, yc)));
    v[3] = mul2(Wv[5], mul2(xc, yc));
#pragma unroll
    for (int j = 0; j < 5; ++j) {
        const int sA = (kk + 1 + j) % 11;    // row offset j
        const int sB = (kk + 11 - j) % 11;   // row offset 10-j
        const u64 xa = (j == 0 && useOld) ? ox : xr[sA];
        const u64 ya = (j == 0 && useOld) ? oy : yr[sA];
        const u64 xb = xr[sB];
        const u64 yb = yr[sB];
        v[0] = fma2(Wv[j], add2(xa, xb), v[0]);
        v[1] = fma2(Wv[j], add2(ya, yb), v[1]);
        const u64 pa = fma2(xa, xa, mul2(ya, ya));
        const u64 pb = fma2(xb, xb, mul2(yb, yb));
        v[2] = fma2(Wv[j], add2(pa, pb), v[2]);
        v[3] = fma2(Wv[j], fma2(xa, ya, mul2(xb, yb)), v[3]);
    }
}

// h[0]=mu_x, h[1]=mu_y, h[2]=blur(x^2+y^2), h[3]=blur(xy)
static __device__ __forceinline__ float ssim2(const u64 h[4], u64 C1_2, u64 C2_2,
                                              u64 EPS2, u64 NEG1, u64 TWO) {
    const u64 musq = fma2(h[0], h[0], mul2(h[1], h[1]));  // mu_x^2 + mu_y^2
    const u64 mxy  = mul2(h[0], h[1]);
    const u64 ssum = fma2(musq, NEG1, h[2]);              // sigma_x^2 + sigma_y^2
    const u64 sxy  = fma2(mxy,  NEG1, h[3]);
    // 2*mxy is exact, so fma(mxy,2,C1) == add(mxy+mxy, C1) bitwise.
    const u64 num = mul2(fma2(mxy, TWO, C1_2), fma2(sxy, TWO, C2_2));
    const u64 den = add2(mul2(add2(musq, C1_2), add2(ssum, C2_2)), EPS2);
    float n0, n1, d0, d1;
    upk2(num, n0, n1);
    upk2(den, d0, d1);
    return __fdividef(n0, d0) + __fdividef(n1, d1);
}

__global__ __launch_bounds__(NT, 2)
void ssim_main(const float* __restrict__ X, const float* __restrict__ Y,
               float* __restrict__ out) {
    // Double-buffered 2-row exchange: [phase-buffer][row-in-phase][quantity][RB]
    __shared__ __align__(16) float sq[2][2][4][RB];
    __shared__ float wsum[NT / 32];
    __shared__ int amLast;

    const int t = threadIdx.x;              // vertical role: cols (2t, 2t+1)
    const int b = blockIdx.x;               // 0..295

    // ---- Balanced tiling: planes 0-7 have 7 chunks, planes 8-47 have 6 ----
    int plane, r0, ch;
    if (b < 56) {
        plane = b / 7;
        const int c = b % 7;                 // sizes 74,74,74,74,72,72,72
        ch = (c < 4) ? 74 : 72;
        r0 = (c < 4) ? 74 * c : 296 + 72 * (c - 4);
    } else {
        const int bb = b - 56;
        plane = 8 + bb / 6;
        const int c = bb % 6;                // sizes 86,86,86,86,84,84
        ch = (c < 4) ? 86 : 84;
        r0 = (c < 4) ? 86 * c : 344 + 84 * (c - 4);
    }
    const int riter = ch + 10;

    const int hrow = t >> 7;                // horizontal role: row-in-phase
    const int u    = t & 127;               // horizontal role: cols 4u..4u+3

    const float2* __restrict__ X2 =
        reinterpret_cast<const float2*>(X + (size_t)plane * W * H);
    const float2* __restrict__ Y2 =
        reinterpret_cast<const float2*>(Y + (size_t)plane * W * H);

    // Zero pads once (stores below only touch idx [6 .. 517]).
    if (t < 6) {
#pragma unroll
        for (int pb = 0; pb < 2; ++pb)
#pragma unroll
            for (int r = 0; r < 2; ++r)
#pragma unroll
                for (int q = 0; q < 4; ++q) sq[pb][r][q][t] = 0.f;
    }
    if (t < 10) {
#pragma unroll
        for (int pb = 0; pb < 2; ++pb)
#pragma unroll
            for (int r = 0; r < 2; ++r)
#pragma unroll
                for (int q = 0; q < 4; ++q) sq[pb][r][q][518 + t] = 0.f;
    }

    const float Gw[6] = {0.00102838f, 0.00759875f, 0.03600077f,
                         0.10936070f, 0.21300554f, 0.26601172f};
    u64 Wv[6];
#pragma unroll
    for (int i = 0; i < 6; ++i) Wv[i] = pk2(Gw[i], Gw[i]);
    const u64 NEG1 = pk2(-1.f, -1.f);
    const u64 TWO  = pk2(2.f, 2.f);
    const u64 C1_2 = pk2(C1c, C1c);
    const u64 C2_2 = pk2(C2c, C2c);
    const u64 EPS2 = pk2(1e-8f, 1e-8f);

    // Register ring: 11 rows of raw x,y (packed column pair).
    u64 xr[11], yr[11];

    // Prefetch rows 0,1 (image rows r0-5, r0-4).
    float2 p0x, p0y, p1x, p1y;
    {
        const int ra = r0 - 5, rb = r0 - 4;
        const bool oa = ((unsigned)ra < (unsigned)H);
        const bool ob = ((unsigned)rb < (unsigned)H);
        p0x = oa ? X2[(size_t)ra * (W / 2) + t] : make_float2(0.f, 0.f);
        p0y = oa ? Y2[(size_t)ra * (W / 2) + t] : make_float2(0.f, 0.f);
        p1x = ob ? X2[(size_t)rb * (W / 2) + t] : make_float2(0.f, 0.f);
        p1y = ob ? Y2[(size_t)rb * (W / 2) + t] : make_float2(0.f, 0.f);
    }

    float acc = 0.f;

#pragma unroll 1
    for (int outer = 0; outer < MAXRI; outer += 22) {
#pragma unroll
        for (int ph = 0; ph < 11; ++ph) {
            const int rr = outer + 2 * ph;          // even; rows rr, rr+1
            if (rr < riter) {
                const int k0 = (2 * ph) % 11;       // compile-time slots
                const int k1 = (2 * ph + 1) % 11;

                // Save row rr-10 (slot k1) before the ring writes clobber it;
                // vert(k0)'s j=0 tap reads it from these registers.
                const u64 ox = xr[k1], oy = yr[k1];

                xr[k0] = pkf2(p0x); yr[k0] = pkf2(p0y);
                xr[k1] = pkf2(p1x); yr[k1] = pkf2(p1y);

                // Prefetch rows rr+2, rr+3 at phase top (R5 placement:
                // full-phase overlap with compute below).
                {
                    const int ra = r0 - 5 + rr + 2, rb = ra + 1;
                    const bool oa = (rr + 2 < riter) && ((unsigned)ra < (unsigned)H);
                    const bool ob = (rr + 3 < riter) && ((unsigned)rb < (unsigned)H);
                    p0x = oa ? X2[(size_t)ra * (W / 2) + t] : make_float2(0.f, 0.f);
                    p0y = oa ? Y2[(size_t)ra * (W / 2) + t] : make_float2(0.f, 0.f);
                    p1x = ob ? X2[(size_t)rb * (W / 2) + t] : make_float2(0.f, 0.f);
                    p1y = ob ? Y2[(size_t)rb * (W / 2) + t] : make_float2(0.f, 0.f);
                }

                if (rr >= 10) {
                    const int pb = (rr >> 1) & 1;   // phase buffer

                    // ---- Vertical blur for output rows rr-10, rr-9 ----
                    u64 v0[4], v1[4];
                    vert(xr, yr, ox, oy, true,  k0, Wv, v0);
                    vert(xr, yr, ox, oy, false, k1, Wv, v1);

                    // ---- Exchange: aligned STS.64 (idx 6+2t is even) ----
#pragma unroll
                    for (int q = 0; q < 4; ++q) {
                        *reinterpret_cast<u64*>(&sq[pb][0][q][6 + 2 * t]) = v0[q];
                        *reinterpret_cast<u64*>(&sq[pb][1][q][6 + 2 * t]) = v1[q];
                    }
                    __syncthreads();     // one barrier per 2-row phase

                    // ---- Horizontal: 4 cols of one row per thread ----
                    u64 hA[4], hB[4];    // pairs m=0 (cols 4u,4u+1), m=1
#pragma unroll
                    for (int q = 0; q < 4; ++q) {
                        const float4* P =
                            reinterpret_cast<const float4*>(&sq[pb][hrow][q][4 * u]);
                        const float4 a = P[0], bq = P[1], cq = P[2], d = P[3];
                        // U_j = cols (4u-6+2j, 4u-5+2j), j=0..7
                        const u64 U0 = pk2(a.x, a.y),  U1 = pk2(a.z, a.w);
                        const u64 U2 = pk2(bq.x, bq.y), U3 = pk2(bq.z, bq.w);
                        const u64 U4 = pk2(cq.x, cq.y), U5 = pk2(cq.z, cq.w);
                        const u64 U6 = pk2(d.x, d.y),  U7 = pk2(d.z, d.w);
                        const u64 A2 = add2(U2, U3), A3 = add2(U3, U4), A4 = add2(U4, U5);
                        const u64 B1 = add2(U1, U4), B2 = add2(U2, U5), B3 = add2(U3, U6);
                        const u64 Cg0 = add2(U0, U5), Cg1 = add2(U1, U6), Cg2 = add2(U2, U7);
                        // m = 0
                        u64 h = mul2(Wv[5], U3);
                        h = fma2(Wv[3], add2(U2, U4), h);
                        h = fma2(Wv[1], add2(U1, U5), h);
                        h = fma2(Wv[4], hilo(A2, A3), h);
                        h = fma2(Wv[2], hilo(B1, B2), h);
                        h = fma2(Wv[0], hilo(Cg0, Cg1), h);
                        hA[q] = h;
                        // m = 1
                        u64 g = mul2(Wv[5], U4);
                        g = fma2(Wv[3], add2(U3, U5), g);
                        g = fma2(Wv[1], add2(U2, U6), g);
                        g = fma2(Wv[4], hilo(A3, A4), g);
                        g = fma2(Wv[2], hilo(B2, B3), g);
                        g = fma2(Wv[0], hilo(Cg1, Cg2), g);
                        hB[q] = g;
                    }

                    acc += ssim2(hA, C1_2, C2_2, EPS2, NEG1, TWO);
                    acc += ssim2(hB, C1_2, C2_2, EPS2, NEG1, TWO);
                    // No second barrier: double-buffered across phases.
                }
            }
        }
    }

    // ---- Deterministic block reduction ----
#pragma unroll
    for (int off = 16; off > 0; off >>= 1)
        acc += __shfl_down_sync(0xffffffffu, acc, off);
    const int lane = t & 31, wid = t >> 5;
    if (lane == 0) wsum[wid] = acc;
    __syncthreads();
    if (wid == 0) {
        float v = (lane < NT / 32) ? wsum[lane] : 0.f;
#pragma unroll
        for (int off = 4; off > 0; off >>= 1)
            v += __shfl_down_sync(0xffffffffu, v, off);
        if (lane == 0) g_partials[b] = v;
    }

    // ---- Fused finalize: last block reduces all partials ----
    if (t == 0) {
        __threadfence();
        const int prev = atomicAdd(&g_count, 1);
        amLast = (prev == NBLK - 1);
    }
    __syncthreads();
    if (amLast) {
        float s = (t < NBLK) ? g_partials[t] : 0.f;
        if (t + 256 < NBLK) s += g_partials[t + 256];
#pragma unroll
        for (int off = 16; off > 0; off >>= 1)
            s += __shfl_down_sync(0xffffffffu, s, off);
        if (lane == 0) wsum[wid] = s;
        __syncthreads();
        if (wid == 0) {
            float v = (lane < NT / 32) ? wsum[lane] : 0.f;
#pragma unroll
            for (int off = 4; off > 0; off >>= 1)
                v += __shfl_down_sync(0xffffffffu, v, off);
            if (lane == 0) {
                constexpr float invN = 1.0f / (float)((size_t)PLANES * W * H);
                out[0] = 1.0f - v * invN;
                g_count = 0;        // reset for next graph replay
            }
        }
    }
}

extern "C" void kernel_launch(void* const* d_in, const int* in_sizes, int n_in,
                              void* d_out, int out_size) {
    const float* X = (const float*)d_in[0];
    const float* Y = (const float*)d_in[1];
    float* out = (float*)d_out;

    ssim_main<<<NBLK, NT>>>(X, Y, out);   // 296 blocks = 148 SMs x occ 2
}

// round 11
// speedup vs baseline: 1.0931x; 1.0310x over previous
#include <cuda_runtime.h>

namespace {
constexpr int W      = 512;
constexpr int H      = 512;
constexpr int PLANES = 16 * 3;         // 48
constexpr int NBLK   = 296;            // 148 SMs x occ 2, exactly one wave
constexpr int NT     = 256;
constexpr int RB     = 528;            // row buffer floats (stride mult of 16B)
constexpr int MAXRI  = 96;             // max riter = 86 + 10; 96 = 8 * 12
constexpr float C1c  = 1e-4f;
constexpr float C2c  = 9e-4f;
}

__device__ float g_partials[NBLK];
__device__ int   g_count = 0;

// ---------------- packed f32x2 helpers (sm_103a) ----------------
using u64 = unsigned long long;

static __device__ __forceinline__ u64 pk2(float lo, float hi) {
    u64 r; asm("mov.b64 %0, {%1, %2};" : "=l"(r) : "f"(lo), "f"(hi)); return r;
}
static __device__ __forceinline__ u64 pkf2(float2 v) { return pk2(v.x, v.y); }
static __device__ __forceinline__ void upk2(u64 v, float& lo, float& hi) {
    asm("mov.b64 {%0, %1}, %2;" : "=f"(lo), "=f"(hi) : "l"(v));
}
static __device__ __forceinline__ u64 fma2(u64 a, u64 b, u64 c) {
    u64 d; asm("fma.rn.f32x2 %0, %1, %2, %3;" : "=l"(d) : "l"(a), "l"(b), "l"(c)); return d;
}
static __device__ __forceinline__ u64 add2(u64 a, u64 b) {
    u64 d; asm("add.rn.f32x2 %0, %1, %2;" : "=l"(d) : "l"(a), "l"(b)); return d;
}
static __device__ __forceinline__ u64 mul2(u64 a, u64 b) {
    u64 d; asm("mul.rn.f32x2 %0, %1, %2;" : "=l"(d) : "l"(a), "l"(b)); return d;
}
// (a.hi, b.lo) as a packed pair
static __device__ __forceinline__ u64 hilo(u64 a, u64 b) {
    float al, ah, bl, bh; upk2(a, al, ah); upk2(b, bl, bh); return pk2(ah, bl);
}

// Vertical 11-tap blur of x, y, p = x^2+y^2, q = x*y from a 12-slot ring.
// Output row "out": input row out+j lives in slot (kk + 2 + j) % 12, where
// kk = out+10 (mod 12) is the slot of the newest needed row. All indices
// compile-time after unroll.
static __device__ __forceinline__ void vert(const u64 xr[12], const u64 yr[12],
                                            int kk, const u64 Wv[6], u64 v[4]) {
    const int sC = (kk + 7) % 12;        // row offset 5 (center)
    const u64 xc = xr[sC], yc = yr[sC];
    v[0] = mul2(Wv[5], xc);
    v[1] = mul2(Wv[5], yc);
    v[2] = mul2(Wv[5], fma2(xc, xc, mul2(yc, yc)));
    v[3] = mul2(Wv[5], mul2(xc, yc));
#pragma unroll
    for (int j = 0; j < 5; ++j) {
        const int sA = (kk + 2 + j) % 12;    // row offset j
        const int sB = (kk + 12 - j) % 12;   // row offset 10-j
        const u64 xa = xr[sA], xb = xr[sB];
        const u64 ya = yr[sA], yb = yr[sB];
        v[0] = fma2(Wv[j], add2(xa, xb), v[0]);
        v[1] = fma2(Wv[j], add2(ya, yb), v[1]);
        const u64 pa = fma2(xa, xa, mul2(ya, ya));
        const u64 pb = fma2(xb, xb, mul2(yb, yb));
        v[2] = fma2(Wv[j], add2(pa, pb), v[2]);
        v[3] = fma2(Wv[j], fma2(xa, ya, mul2(xb, yb)), v[3]);
    }
}

// h[0]=mu_x, h[1]=mu_y, h[2]=blur(x^2+y^2), h[3]=blur(xy)
static __device__ __forceinline__ float ssim2(const u64 h[4], u64 C1_2, u64 C2_2,
                                              u64 EPS2, u64 NEG1, u64 TWO) {
    const u64 musq = fma2(h[0], h[0], mul2(h[1], h[1]));  // mu_x^2 + mu_y^2
    const u64 mxy  = mul2(h[0], h[1]);
    const u64 ssum = fma2(musq, NEG1, h[2]);              // sigma_x^2 + sigma_y^2
    const u64 sxy  = fma2(mxy,  NEG1, h[3]);
    const u64 num = mul2(fma2(mxy, TWO, C1_2), fma2(sxy, TWO, C2_2));
    const u64 den = add2(mul2(add2(musq, C1_2), add2(ssum, C2_2)), EPS2);
    float n0, n1, d0, d1;
    upk2(num, n0, n1);
    upk2(den, d0, d1);
    return __fdividef(n0, d0) + __fdividef(n1, d1);
}

__global__ __launch_bounds__(NT, 2)
void ssim_main(const float* __restrict__ X, const float* __restrict__ Y,
               float* __restrict__ out) {
    // Double-buffered 2-row exchange: [phase-buffer][row-in-phase][quantity][RB]
    __shared__ __align__(16) float sq[2][2][4][RB];
    __shared__ float wsum[NT / 32];
    __shared__ int amLast;

    const int t = threadIdx.x;              // vertical role: cols (2t, 2t+1)
    const int b = blockIdx.x;               // 0..295

    // ---- Balanced tiling: planes 0-7 have 7 chunks, planes 8-47 have 6 ----
    int plane, r0, ch;
    if (b < 56) {
        plane = b / 7;
        const int c = b % 7;                 // sizes 74,74,74,74,72,72,72
        ch = (c < 4) ? 74 : 72;
        r0 = (c < 4) ? 74 * c : 296 + 72 * (c - 4);
    } else {
        const int bb = b - 56;
        plane = 8 + bb / 6;
        const int c = bb % 6;                // sizes 86,86,86,86,84,84
        ch = (c < 4) ? 86 : 84;
        r0 = (c < 4) ? 86 * c : 344 + 84 * (c - 4);
    }
    const int riter = ch + 10;

    const int hrow = t >> 7;                // horizontal role: row-in-phase
    const int u    = t & 127;               // horizontal role: cols 4u..4u+3

    const float2* __restrict__ X2 =
        reinterpret_cast<const float2*>(X + (size_t)plane * W * H);
    const float2* __restrict__ Y2 =
        reinterpret_cast<const float2*>(Y + (size_t)plane * W * H);

    // Zero pads once (stores below only touch idx [6 .. 517]).
    if (t < 6) {
#pragma unroll
        for (int pb = 0; pb < 2; ++pb)
#pragma unroll
            for (int r = 0; r < 2; ++r)
#pragma unroll
                for (int q = 0; q < 4; ++q) sq[pb][r][q][t] = 0.f;
    }
    if (t < 10) {
#pragma unroll
        for (int pb = 0; pb < 2; ++pb)
#pragma unroll
            for (int r = 0; r < 2; ++r)
#pragma unroll
                for (int q = 0; q < 4; ++q) sq[pb][r][q][518 + t] = 0.f;
    }

    const float Gw[6] = {0.00102838f, 0.00759875f, 0.03600077f,
                         0.10936070f, 0.21300554f, 0.26601172f};
    u64 Wv[6];
#pragma unroll
    for (int i = 0; i < 6; ++i) Wv[i] = pk2(Gw[i], Gw[i]);
    const u64 NEG1 = pk2(-1.f, -1.f);
    const u64 TWO  = pk2(2.f, 2.f);
    const u64 C1_2 = pk2(C1c, C1c);
    const u64 C2_2 = pk2(C2c, C2c);
    const u64 EPS2 = pk2(1e-8f, 1e-8f);

    // 12-slot register ring of raw x,y (packed column pair). Row r -> slot r%12.
    u64 xr[12], yr[12];

    // Prefetch rows 0,1 (image rows r0-5, r0-4).
    float2 p0x, p0y, p1x, p1y;
    {
        const int ra = r0 - 5, rb = r0 - 4;
        const bool oa = ((unsigned)ra < (unsigned)H);
        const bool ob = ((unsigned)rb < (unsigned)H);
        p0x = oa ? X2[(size_t)ra * (W / 2) + t] : make_float2(0.f, 0.f);
        p0y = oa ? Y2[(size_t)ra * (W / 2) + t] : make_float2(0.f, 0.f);
        p1x = ob ? X2[(size_t)rb * (W / 2) + t] : make_float2(0.f, 0.f);
        p1y = ob ? Y2[(size_t)rb * (W / 2) + t] : make_float2(0.f, 0.f);
    }

    float acc = 0.f;

    // Inner unroll of 6 phases (12 rows) -- ring period. Slots compile-time.
#pragma unroll 1
    for (int outer = 0; outer < MAXRI; outer += 12) {
#pragma unroll
        for (int ph = 0; ph < 6; ++ph) {
            const int rr = outer + 2 * ph;          // even; rows rr, rr+1
            if (rr < riter) {
                const int k0 = 2 * ph;              // slot of row rr
                const int k1 = 2 * ph + 1;          // slot of row rr+1

                // Slots k0,k1 hold rows rr-12, rr-11 -- needed by no vert.
                // Safe to overwrite before both verts (12-ring property).
                xr[k0] = pkf2(p0x); yr[k0] = pkf2(p0y);
                xr[k1] = pkf2(p1x); yr[k1] = pkf2(p1y);

                // Prefetch rows rr+2, rr+3 at phase top (full-phase overlap).
                {
                    const int ra = r0 - 5 + rr + 2, rb = ra + 1;
                    const bool oa = (rr + 2 < riter) && ((unsigned)ra < (unsigned)H);
                    const bool ob = (rr + 3 < riter) && ((unsigned)rb < (unsigned)H);
                    p0x = oa ? X2[(size_t)ra * (W / 2) + t] : make_float2(0.f, 0.f);
                    p0y = oa ? Y2[(size_t)ra * (W / 2) + t] : make_float2(0.f, 0.f);
                    p1x = ob ? X2[(size_t)rb * (W / 2) + t] : make_float2(0.f, 0.f);
                    p1y = ob ? Y2[(size_t)rb * (W / 2) + t] : make_float2(0.f, 0.f);
                }

                if (rr >= 10) {
                    const int pb = (rr >> 1) & 1;   // phase buffer

                    // ---- Vertical blur for output rows rr-10, rr-9 ----
                    u64 v0[4], v1[4];
                    vert(xr, yr, k0, Wv, v0);
                    vert(xr, yr, k1, Wv, v1);

                    // ---- Exchange: aligned STS.64 (idx 6+2t is even) ----
#pragma unroll
                    for (int q = 0; q < 4; ++q) {
                        *reinterpret_cast<u64*>(&sq[pb][0][q][6 + 2 * t]) = v0[q];
                        *reinterpret_cast<u64*>(&sq[pb][1][q][6 + 2 * t]) = v1[q];
                    }
                    __syncthreads();     // one barrier per 2-row phase

                    // ---- Horizontal: 4 cols of one row per thread ----
                    u64 hA[4], hB[4];    // pairs m=0 (cols 4u,4u+1), m=1
#pragma unroll
                    for (int q = 0; q < 4; ++q) {
                        const float4* P =
                            reinterpret_cast<const float4*>(&sq[pb][hrow][q][4 * u]);
                        const float4 a = P[0], bq = P[1], cq = P[2], d = P[3];
                        // U_j = cols (4u-6+2j, 4u-5+2j), j=0..7
                        const u64 U0 = pk2(a.x, a.y),  U1 = pk2(a.z, a.w);
                        const u64 U2 = pk2(bq.x, bq.y), U3 = pk2(bq.z, bq.w);
                        const u64 U4 = pk2(cq.x, cq.y), U5 = pk2(cq.z, cq.w);
                        const u64 U6 = pk2(d.x, d.y),  U7 = pk2(d.z, d.w);
                        const u64 A2 = add2(U2, U3), A3 = add2(U3, U4), A4 = add2(U4, U5);
                        const u64 B1 = add2(U1, U4), B2 = add2(U2, U5), B3 = add2(U3, U6);
                        const u64 Cg0 = add2(U0, U5), Cg1 = add2(U1, U6), Cg2 = add2(U2, U7);
                        // m = 0
                        u64 h = mul2(Wv[5], U3);
                        h = fma2(Wv[3], add2(U2, U4), h);
                        h = fma2(Wv[1], add2(U1, U5), h);
                        h = fma2(Wv[4], hilo(A2, A3), h);
                        h = fma2(Wv[2], hilo(B1, B2), h);
                        h = fma2(Wv[0], hilo(Cg0, Cg1), h);
                        hA[q] = h;
                        // m = 1
                        u64 g = mul2(Wv[5], U4);
                        g = fma2(Wv[3], add2(U3, U5), g);
                        g = fma2(Wv[1], add2(U2, U6), g);
                        g = fma2(Wv[4], hilo(A3, A4), g);
                        g = fma2(Wv[2], hilo(B2, B3), g);
                        g = fma2(Wv[0], hilo(Cg1, Cg2), g);
                        hB[q] = g;
                    }

                    acc += ssim2(hA, C1_2, C2_2, EPS2, NEG1, TWO);
                    acc += ssim2(hB, C1_2, C2_2, EPS2, NEG1, TWO);
                    // No second barrier: double-buffered across phases.
                }
            }
        }
    }

    // ---- Deterministic block reduction ----
#pragma unroll
    for (int off = 16; off > 0; off >>= 1)
        acc += __shfl_down_sync(0xffffffffu, acc, off);
    const int lane = t & 31, wid = t >> 5;
    if (lane == 0) wsum[wid] = acc;
    __syncthreads();
    if (wid == 0) {
        float v = (lane < NT / 32) ? wsum[lane] : 0.f;
#pragma unroll
        for (int off = 4; off > 0; off >>= 1)
            v += __shfl_down_sync(0xffffffffu, v, off);
        if (lane == 0) g_partials[b] = v;
    }

    // ---- Fused finalize: last block reduces all partials ----
    if (t == 0) {
        __threadfence();
        const int prev = atomicAdd(&g_count, 1);
        amLast = (prev == NBLK - 1);
    }
    __syncthreads();
    if (amLast) {
        float s = (t < NBLK) ? g_partials[t] : 0.f;
        if (t + 256 < NBLK) s += g_partials[t + 256];
#pragma unroll
        for (int off = 16; off > 0; off >>= 1)
            s += __shfl_down_sync(0xffffffffu, s, off);
        if (lane == 0) wsum[wid] = s;
        __syncthreads();
        if (wid == 0) {
            float v = (lane < NT / 32) ? wsum[lane] : 0.f;
#pragma unroll
            for (int off = 4; off > 0; off >>= 1)
                v += __shfl_down_sync(0xffffffffu, v, off);
            if (lane == 0) {
                constexpr float invN = 1.0f / (float)((size_t)PLANES * W * H);
                out[0] = 1.0f - v * invN;
                g_count = 0;        // reset for next graph replay
            }
        }
    }
}

extern "C" void kernel_launch(void* const* d_in, const int* in_sizes, int n_in,
                              void* d_out, int out_size) {
    const float* X = (const float*)d_in[0];
    const float* Y = (const float*)d_in[1];
    float* out = (float*)d_out;

    ssim_main<<<NBLK, NT>>>(X, Y, out);   // 296 blocks = 148 SMs x occ 2
}